// round 11
// baseline (speedup 1.0000x reference)
#include <cuda_runtime.h>

#define NN 100000
#define NE 3200000
#define NG 64
#define NB 100               // scan blocks
#define NPB 1000             // nodes per scan block (NB*NPB == NN)

typedef unsigned long long ull;

// ---------------- scratch (device globals; no allocations allowed) ----------
__device__ float d_deg[NN];          // weighted degree -> dinv (in place)
__device__ int   d_cnt[NN];          // edge count per dst
__device__ int   d_ptr[NN + 1];      // CSR row offsets
__device__ int   d_fill[NN];         // scatter cursors
__device__ int   d_bsum[NB];         // per-block count totals
__device__ int   d_boff[NB];         // exclusive block offsets
__device__ int2  d_csr[NE];          // {src, __float_as_int(norm)}
__device__ float d_h1pre[NN * 64];   // x @ W1
__device__ float d_h1out[NN * 64];   // conv1 aggregated (pre bias/relu)
__device__ float d_h2pre[NN * 32];   // relu(h1out+b1) @ W2
__device__ float d_pooled[NG * 32];

// --------- side stream + events for captured fork/join (created pre-main) ---
static cudaStream_t g_s2;
static cudaEvent_t  g_evF, g_evJ;
static struct StreamInit {
    StreamInit() {
        cudaStreamCreateWithFlags(&g_s2, cudaStreamNonBlocking);
        cudaEventCreateWithFlags(&g_evF, cudaEventDisableTiming);
        cudaEventCreateWithFlags(&g_evJ, cudaEventDisableTiming);
    }
} g_streamInit;

// ---------------- f32x2 helpers (Blackwell packed fp32) ---------------------
__device__ __forceinline__ ull pk2(float x) {
    ull r;
    asm("mov.b64 %0, {%1, %1};" : "=l"(r) : "f"(x));
    return r;
}
__device__ __forceinline__ void fma2(ull& d, ull a, ull b) {
    asm("fma.rn.f32x2 %0, %1, %2, %0;" : "+l"(d) : "l"(a), "l"(b));
}
__device__ __forceinline__ float2 up2(ull v) {
    float2 f;
    asm("mov.b64 {%0, %1}, %2;" : "=f"(f.x), "=f"(f.y) : "l"(v));
    return f;
}

// ---------------- init -------------------------------------------------------
__global__ void k_init() {
    int i = blockIdx.x * 256 + threadIdx.x;
    if (i < NN) { d_deg[i] = 1.0f; d_cnt[i] = 0; }   // self-loop weight 1
    if (i < NG * 32) d_pooled[i] = 0.0f;             // relu outputs >= 0
}

// ---------------- edge histogram ---------------------------------------------
__global__ void __launch_bounds__(256) k_hist(const int* __restrict__ ei,
                                              const float* __restrict__ ew) {
    int e = blockIdx.x * 256 + threadIdx.x;
    if (e >= NE) return;
    int d = ei[NE + e];
    atomicAdd(&d_deg[d], ew[e]);
    atomicAdd(&d_cnt[d], 1);
}

// ---- hierarchical scan of d_cnt -> d_ptr (exclusive); rsqrt fused ----------
__global__ void __launch_bounds__(256) k_scanA() {    // per-block totals
    __shared__ int sm[8];
    int b = blockIdx.x, t = threadIdx.x;
    int s = 0;
    for (int i = t; i < NPB; i += 256) s += d_cnt[b * NPB + i];
#pragma unroll
    for (int o = 16; o; o >>= 1) s += __shfl_xor_sync(0xffffffffu, s, o);
    if ((t & 31) == 0) sm[t >> 5] = s;
    __syncthreads();
    if (t == 0) {
        int tot = 0;
#pragma unroll
        for (int i = 0; i < 8; i++) tot += sm[i];
        d_bsum[b] = tot;
    }
    // fused: deg -> rsqrt(deg)  (deg >= 1 always)
    for (int i = b * 256 + t; i < NN; i += NB * 256)
        d_deg[i] = rsqrtf(d_deg[i]);
}

__global__ void __launch_bounds__(128) k_scanB() {    // scan 100 partials
    __shared__ int sm[128];
    int t = threadIdx.x;
    sm[t] = (t < NB) ? d_bsum[t] : 0;
    __syncthreads();
#pragma unroll
    for (int off = 1; off < 128; off <<= 1) {
        int v = (t >= off) ? sm[t - off] : 0;
        __syncthreads();
        sm[t] += v;
        __syncthreads();
    }
    if (t < NB) d_boff[t] = sm[t] - d_bsum[t];   // exclusive
    if (t == 0) d_ptr[NN] = NE;
}

__global__ void __launch_bounds__(256) k_scanC() {    // in-block scan + write
    __shared__ int sm[256];
    int b = blockIdx.x, t = threadIdx.x;
    int base = b * NPB;
    int4 c = make_int4(0, 0, 0, 0);
    if (t < NPB / 4) c = ((const int4*)(d_cnt + base))[t];
    int tsum = c.x + c.y + c.z + c.w;
    sm[t] = tsum;
    __syncthreads();
#pragma unroll
    for (int off = 1; off < 256; off <<= 1) {
        int v = (t >= off) ? sm[t - off] : 0;
        __syncthreads();
        sm[t] += v;
        __syncthreads();
    }
    if (t < NPB / 4) {
        int run = d_boff[b] + sm[t] - tsum;
        int i = base + t * 4;
        d_ptr[i] = run;     d_fill[i] = run;     run += c.x;
        d_ptr[i + 1] = run; d_fill[i + 1] = run; run += c.y;
        d_ptr[i + 2] = run; d_fill[i + 2] = run; run += c.z;
        d_ptr[i + 3] = run; d_fill[i + 3] = run;
    }
}

__global__ void k_scatter(const int* __restrict__ ei, const float* __restrict__ ew) {
    int e = blockIdx.x * 256 + threadIdx.x;
    if (e >= NE) return;
    int s = ei[e];
    int d = ei[NE + e];
    float w = d_deg[s] * ew[e] * d_deg[d];
    int pos = atomicAdd(&d_fill[d], 1);
    d_csr[pos] = make_int2(s, __float_as_int(w));
}

// ---------------- GEMM: C[n, COLS] = f(A[n, K]) @ W[K, COLS] ----------------
template <int K, int COLS, int MODE>
__global__ void __launch_bounds__(256) k_gemm(const float* __restrict__ Aarg,
                                              const float* __restrict__ W,
                                              const float* __restrict__ bias) {
    constexpr int CG = COLS / 4;
    constexpr int ROWS = (256 / CG) * 8;
    constexpr int KC = 64;
    __shared__ __align__(16) float Ws[KC * COLS];
    __shared__ __align__(16) float Bs[KC];
    const float* A = (MODE == 1) ? Aarg : d_h1out;
    float* C = (MODE == 1) ? d_h1pre : d_h2pre;

    int t = threadIdx.x;
    int ct = t % CG;
    int rt = t / CG;
    int row0 = blockIdx.x * ROWS + rt * 8;

    const float* ap[8];
#pragma unroll
    for (int i = 0; i < 8; i++) {
        int r = row0 + i;
        if (r > NN - 1) r = NN - 1;
        ap[i] = A + (long long)r * K;
    }

    ull acc[8][2];
#pragma unroll
    for (int i = 0; i < 8; i++) { acc[i][0] = 0ULL; acc[i][1] = 0ULL; }

    for (int k0 = 0; k0 < K; k0 += KC) {
        __syncthreads();
        for (int i = t; i < KC * COLS / 4; i += 256)
            ((float4*)Ws)[i] = ((const float4*)(W + k0 * COLS))[i];
        if (MODE == 2) {
            if (t < KC) Bs[t] = bias[k0 + t];
        }
        __syncthreads();

#pragma unroll 2
        for (int kq = 0; kq < KC / 4; kq++) {
            float4 a[8];
#pragma unroll
            for (int i = 0; i < 8; i++) a[i] = *(const float4*)(ap[i] + k0 + kq * 4);
            if (MODE == 2) {
                float4 b4 = *(const float4*)(Bs + kq * 4);
#pragma unroll
                for (int i = 0; i < 8; i++) {
                    a[i].x = fmaxf(a[i].x + b4.x, 0.0f);
                    a[i].y = fmaxf(a[i].y + b4.y, 0.0f);
                    a[i].z = fmaxf(a[i].z + b4.z, 0.0f);
                    a[i].w = fmaxf(a[i].w + b4.w, 0.0f);
                }
            }
#pragma unroll
            for (int j = 0; j < 4; j++) {
                ulonglong2 w2 = *(const ulonglong2*)(Ws + (kq * 4 + j) * COLS + ct * 4);
#pragma unroll
                for (int i = 0; i < 8; i++) {
                    float av = (j == 0) ? a[i].x : (j == 1) ? a[i].y
                             : (j == 2) ? a[i].z : a[i].w;
                    ull aa = pk2(av);
                    fma2(acc[i][0], aa, w2.x);
                    fma2(acc[i][1], aa, w2.y);
                }
            }
        }
    }

#pragma unroll
    for (int i = 0; i < 8; i++) {
        int r = row0 + i;
        if (r < NN) {
            float2 p0 = up2(acc[i][0]);
            float2 p1 = up2(acc[i][1]);
            *(float4*)(C + (long long)r * COLS + ct * 4) =
                make_float4(p0.x, p0.y, p1.x, p1.y);
        }
    }
}

// -------- agg1: CSR gather, warp/node, smem-staged edge records --------------
__global__ void __launch_bounds__(256) k_agg1() {
    __shared__ int2 es[8][32];
    int t = threadIdx.x;
    int wi = t >> 5;
    int lane = t & 31;
    int node = blockIdx.x * 8 + wi;
    if (node >= NN) return;

    const ull* h1 = (const ull*)d_h1pre;   // float2 rows, 32 per node
    float dv = d_deg[node];
    ull acc = 0ULL;
    fma2(acc, pk2(dv * dv), h1[node * 32 + lane]);   // self-loop

    int beg = d_ptr[node], end = d_ptr[node + 1];
    for (int base = beg; base < end; base += 32) {
        if (base + lane < end) es[wi][lane] = d_csr[base + lane];
        __syncwarp();
        int cnt = end - base; if (cnt > 32) cnt = 32;
        for (int j = 0; j < cnt; j++) {
            int2 q = es[wi][j];                       // broadcast LDS.64
            ull v = h1[q.x * 32 + lane];
            fma2(acc, pk2(__int_as_float(q.y)), v);
        }
        __syncwarp();
    }
    ((ull*)d_h1out)[node * 32 + lane] = acc;
}

// ---- agg2 + fused bias/relu/max-pool tail (h2out eliminated) ----------------
__global__ void __launch_bounds__(256) k_agg2pool(const int* __restrict__ batch,
                                                  const float* __restrict__ b2) {
    __shared__ int2 es[8][32];
    int t = threadIdx.x;
    int wi = t >> 5;
    int lane = t & 31;
    int node = blockIdx.x * 8 + wi;
    if (node >= NN) return;

    float dv = d_deg[node];
    float acc = d_h2pre[node * 32 + lane] * dv * dv;

    int beg = d_ptr[node], end = d_ptr[node + 1];
    for (int base = beg; base < end; base += 32) {
        if (base + lane < end) es[wi][lane] = d_csr[base + lane];
        __syncwarp();
        int cnt = end - base; if (cnt > 32) cnt = 32;
        for (int j = 0; j < cnt; j++) {
            int2 q = es[wi][j];
            acc = fmaf(__int_as_float(q.y), d_h2pre[q.x * 32 + lane], acc);
        }
        __syncwarp();
    }

    // fused pool: v >= 0 so int-compare atomicMax on float bits is valid
    float v = fmaxf(acc + b2[lane], 0.0f);
    int g = batch[node];
    atomicMax((int*)&d_pooled[g * 32 + lane], __float_as_int(v));
}

// ---------------- final linear: out[64,4] = pooled @ Wlin + blin ------------
__global__ void k_final(const float* __restrict__ Wlin, const float* __restrict__ blin,
                        float* __restrict__ out) {
    int t = threadIdx.x;            // 256 = 64*4
    int g = t >> 2;
    int c = t & 3;
    float s = blin[c];
#pragma unroll
    for (int k = 0; k < 32; k++) s += d_pooled[g * 32 + k] * Wlin[k * 4 + c];
    out[g * 4 + c] = s;
}

// ---------------- launch -----------------------------------------------------
extern "C" void kernel_launch(void* const* d_in, const int* in_sizes, int n_in,
                              void* d_out, int out_size) {
    const float* x     = (const float*)d_in[0];
    const int*   ei    = (const int*)d_in[1];
    const float* ew    = (const float*)d_in[2];
    const int*   batch = (const int*)d_in[3];
    const float* W1    = (const float*)d_in[4];
    const float* b1    = (const float*)d_in[5];
    const float* W2    = (const float*)d_in[6];
    const float* b2    = (const float*)d_in[7];
    const float* Wlin  = (const float*)d_in[8];
    const float* blin  = (const float*)d_in[9];
    float* out = (float*)d_out;

    // fork: gemm1 (FMA-bound) on g_s2, CSR build (atomic/LSU-bound) on main.
    cudaEventRecord(g_evF, 0);
    cudaStreamWaitEvent(g_s2, g_evF, 0);
    k_gemm<256, 64, 1><<<(NN + 127) / 128, 256, 0, g_s2>>>(x, W1, nullptr);
    cudaEventRecord(g_evJ, g_s2);

    k_init<<<(NN + 255) / 256, 256>>>();
    k_hist<<<(NE + 255) / 256, 256>>>(ei, ew);
    k_scanA<<<NB, 256>>>();                                    // + rsqrt
    k_scanB<<<1, 128>>>();
    k_scanC<<<NB, 256>>>();
    k_scatter<<<(NE + 255) / 256, 256>>>(ei, ew);

    cudaStreamWaitEvent(0, g_evJ, 0);                          // join
    k_agg1<<<(NN + 7) / 8, 256>>>();

    k_gemm<64, 32, 2><<<(NN + 255) / 256, 256>>>(nullptr, W2, b1);
    k_agg2pool<<<(NN + 7) / 8, 256>>>(batch, b2);              // agg2 + pool

    k_final<<<1, 256>>>(Wlin, blin, out);
}

// round 12
// speedup vs baseline: 1.1583x; 1.1583x over previous
#include <cuda_runtime.h>
#include <cuda_fp16.h>

#define NN 100000
#define NE 3200000
#define NG 64
#define NB 100               // scan blocks
#define NPB 1000             // nodes per scan block (NB*NPB == NN)

typedef unsigned long long ull;

// ---------------- scratch (device globals; no allocations allowed) ----------
__device__ float  d_deg[NN];          // weighted degree -> dinv (in place)
__device__ int    d_cnt[NN];          // edge count per dst
__device__ int    d_ptr[NN + 1];      // CSR row offsets
__device__ int    d_fill[NN];         // scatter cursors
__device__ int    d_bsum[NB];         // per-block count totals
__device__ int    d_boff[NB];         // exclusive block offsets
__device__ int2   d_csr[NE];          // {src, __float_as_int(norm)}
__device__ __half d_h1pre[NN * 64];   // x @ W1            (fp16 gather table)
__device__ float  d_h1out[NN * 64];   // conv1 aggregated  (fp32, read once)
__device__ __half d_h2pre[NN * 32];   // relu(h1out+b1)@W2 (fp16 gather table)
__device__ float  d_h2out[NN * 32];   // conv2 aggregated
__device__ float  d_pooled[NG * 32];

// --------- side stream + events for captured fork/join (created pre-main) ---
static cudaStream_t g_s2;
static cudaEvent_t  g_evF, g_evJ;
static struct StreamInit {
    StreamInit() {
        cudaStreamCreateWithFlags(&g_s2, cudaStreamNonBlocking);
        cudaEventCreateWithFlags(&g_evF, cudaEventDisableTiming);
        cudaEventCreateWithFlags(&g_evJ, cudaEventDisableTiming);
    }
} g_streamInit;

// ---------------- f32x2 helpers (Blackwell packed fp32) ---------------------
__device__ __forceinline__ ull pk2(float x) {
    ull r;
    asm("mov.b64 %0, {%1, %1};" : "=l"(r) : "f"(x));
    return r;
}
__device__ __forceinline__ void fma2(ull& d, ull a, ull b) {
    asm("fma.rn.f32x2 %0, %1, %2, %0;" : "+l"(d) : "l"(a), "l"(b));
}
__device__ __forceinline__ float2 up2(ull v) {
    float2 f;
    asm("mov.b64 {%0, %1}, %2;" : "=f"(f.x), "=f"(f.y) : "l"(v));
    return f;
}

// ---------------- init -------------------------------------------------------
__global__ void k_init() {
    int i = blockIdx.x * 256 + threadIdx.x;
    if (i < NN) { d_deg[i] = 1.0f; d_cnt[i] = 0; }   // self-loop weight 1
    if (i < NG * 32) d_pooled[i] = 0.0f;             // relu outputs >= 0
}

// ---------------- edge histogram ---------------------------------------------
__global__ void __launch_bounds__(256) k_hist(const int* __restrict__ ei,
                                              const float* __restrict__ ew) {
    int e = blockIdx.x * 256 + threadIdx.x;
    if (e >= NE) return;
    int d = ei[NE + e];
    atomicAdd(&d_deg[d], ew[e]);
    atomicAdd(&d_cnt[d], 1);
}

// ---- hierarchical scan of d_cnt -> d_ptr (exclusive); rsqrt fused ----------
__global__ void __launch_bounds__(256) k_scanA() {    // per-block totals
    __shared__ int sm[8];
    int b = blockIdx.x, t = threadIdx.x;
    int s = 0;
    for (int i = t; i < NPB; i += 256) s += d_cnt[b * NPB + i];
#pragma unroll
    for (int o = 16; o; o >>= 1) s += __shfl_xor_sync(0xffffffffu, s, o);
    if ((t & 31) == 0) sm[t >> 5] = s;
    __syncthreads();
    if (t == 0) {
        int tot = 0;
#pragma unroll
        for (int i = 0; i < 8; i++) tot += sm[i];
        d_bsum[b] = tot;
    }
    // fused: deg -> rsqrt(deg)  (deg >= 1 always)
    for (int i = b * 256 + t; i < NN; i += NB * 256)
        d_deg[i] = rsqrtf(d_deg[i]);
}

__global__ void __launch_bounds__(128) k_scanB() {    // scan 100 partials
    __shared__ int sm[128];
    int t = threadIdx.x;
    sm[t] = (t < NB) ? d_bsum[t] : 0;
    __syncthreads();
#pragma unroll
    for (int off = 1; off < 128; off <<= 1) {
        int v = (t >= off) ? sm[t - off] : 0;
        __syncthreads();
        sm[t] += v;
        __syncthreads();
    }
    if (t < NB) d_boff[t] = sm[t] - d_bsum[t];   // exclusive
    if (t == 0) d_ptr[NN] = NE;
}

__global__ void __launch_bounds__(256) k_scanC() {    // in-block scan + write
    __shared__ int sm[256];
    int b = blockIdx.x, t = threadIdx.x;
    int base = b * NPB;
    int4 c = make_int4(0, 0, 0, 0);
    if (t < NPB / 4) c = ((const int4*)(d_cnt + base))[t];
    int tsum = c.x + c.y + c.z + c.w;
    sm[t] = tsum;
    __syncthreads();
#pragma unroll
    for (int off = 1; off < 256; off <<= 1) {
        int v = (t >= off) ? sm[t - off] : 0;
        __syncthreads();
        sm[t] += v;
        __syncthreads();
    }
    if (t < NPB / 4) {
        int run = d_boff[b] + sm[t] - tsum;
        int i = base + t * 4;
        d_ptr[i] = run;     d_fill[i] = run;     run += c.x;
        d_ptr[i + 1] = run; d_fill[i + 1] = run; run += c.y;
        d_ptr[i + 2] = run; d_fill[i + 2] = run; run += c.z;
        d_ptr[i + 3] = run; d_fill[i + 3] = run;
    }
}

__global__ void k_scatter(const int* __restrict__ ei, const float* __restrict__ ew) {
    int e = blockIdx.x * 256 + threadIdx.x;
    if (e >= NE) return;
    int s = ei[e];
    int d = ei[NE + e];
    float w = d_deg[s] * ew[e] * d_deg[d];
    int pos = atomicAdd(&d_fill[d], 1);
    d_csr[pos] = make_int2(s, __float_as_int(w));
}

// ---------------- GEMM: C[n, COLS] = f(A[n, K]) @ W[K, COLS] ----------------
// MODE 1: A = x, C = d_h1pre (fp16). MODE 2: A = relu(d_h1out+b1), C = d_h2pre (fp16).
template <int K, int COLS, int MODE>
__global__ void __launch_bounds__(256) k_gemm(const float* __restrict__ Aarg,
                                              const float* __restrict__ W,
                                              const float* __restrict__ bias) {
    constexpr int CG = COLS / 4;
    constexpr int ROWS = (256 / CG) * 8;
    constexpr int KC = 64;
    __shared__ __align__(16) float Ws[KC * COLS];
    __shared__ __align__(16) float Bs[KC];
    const float* A = (MODE == 1) ? Aarg : d_h1out;

    int t = threadIdx.x;
    int ct = t % CG;
    int rt = t / CG;
    int row0 = blockIdx.x * ROWS + rt * 8;

    const float* ap[8];
#pragma unroll
    for (int i = 0; i < 8; i++) {
        int r = row0 + i;
        if (r > NN - 1) r = NN - 1;
        ap[i] = A + (long long)r * K;
    }

    ull acc[8][2];
#pragma unroll
    for (int i = 0; i < 8; i++) { acc[i][0] = 0ULL; acc[i][1] = 0ULL; }

    for (int k0 = 0; k0 < K; k0 += KC) {
        __syncthreads();
        for (int i = t; i < KC * COLS / 4; i += 256)
            ((float4*)Ws)[i] = ((const float4*)(W + k0 * COLS))[i];
        if (MODE == 2) {
            if (t < KC) Bs[t] = bias[k0 + t];
        }
        __syncthreads();

#pragma unroll 2
        for (int kq = 0; kq < KC / 4; kq++) {
            float4 a[8];
#pragma unroll
            for (int i = 0; i < 8; i++) a[i] = *(const float4*)(ap[i] + k0 + kq * 4);
            if (MODE == 2) {
                float4 b4 = *(const float4*)(Bs + kq * 4);
#pragma unroll
                for (int i = 0; i < 8; i++) {
                    a[i].x = fmaxf(a[i].x + b4.x, 0.0f);
                    a[i].y = fmaxf(a[i].y + b4.y, 0.0f);
                    a[i].z = fmaxf(a[i].z + b4.z, 0.0f);
                    a[i].w = fmaxf(a[i].w + b4.w, 0.0f);
                }
            }
#pragma unroll
            for (int j = 0; j < 4; j++) {
                ulonglong2 w2 = *(const ulonglong2*)(Ws + (kq * 4 + j) * COLS + ct * 4);
#pragma unroll
                for (int i = 0; i < 8; i++) {
                    float av = (j == 0) ? a[i].x : (j == 1) ? a[i].y
                             : (j == 2) ? a[i].z : a[i].w;
                    ull aa = pk2(av);
                    fma2(acc[i][0], aa, w2.x);
                    fma2(acc[i][1], aa, w2.y);
                }
            }
        }
    }

    __half2* C = (MODE == 1) ? (__half2*)d_h1pre : (__half2*)d_h2pre;
#pragma unroll
    for (int i = 0; i < 8; i++) {
        int r = row0 + i;
        if (r < NN) {
            float2 p0 = up2(acc[i][0]);
            float2 p1 = up2(acc[i][1]);
            C[r * (COLS / 2) + ct * 2]     = __floats2half2_rn(p0.x, p0.y);
            C[r * (COLS / 2) + ct * 2 + 1] = __floats2half2_rn(p1.x, p1.y);
        }
    }
}

// -------- agg1: CSR gather (fp16 table), warp/node, smem-staged --------------
__global__ void __launch_bounds__(256) k_agg1() {
    __shared__ int2 es[8][32];
    int t = threadIdx.x;
    int wi = t >> 5;
    int lane = t & 31;
    int node = blockIdx.x * 8 + wi;
    if (node >= NN) return;

    const __half2* h1 = (const __half2*)d_h1pre;   // 32 half2 per node row
    float dv = d_deg[node];
    float sl = dv * dv;
    float2 acc;
    {
        float2 v = __half22float2(h1[node * 32 + lane]);
        acc.x = v.x * sl;
        acc.y = v.y * sl;
    }

    int beg = d_ptr[node], end = d_ptr[node + 1];
    for (int base = beg; base < end; base += 32) {
        if (base + lane < end) es[wi][lane] = d_csr[base + lane];
        __syncwarp();
        int cnt = end - base; if (cnt > 32) cnt = 32;
        for (int j = 0; j < cnt; j++) {
            int2 q = es[wi][j];                       // broadcast LDS.64
            float w = __int_as_float(q.y);
            float2 v = __half22float2(h1[q.x * 32 + lane]);
            acc.x = fmaf(w, v.x, acc.x);
            acc.y = fmaf(w, v.y, acc.y);
        }
        __syncwarp();
    }
    ((float2*)d_h1out)[node * 32 + lane] = acc;
}

// -------- agg2: CSR gather (fp16 table), warp/node, smem-staged --------------
__global__ void __launch_bounds__(256) k_agg2() {
    __shared__ int2 es[8][32];
    int t = threadIdx.x;
    int wi = t >> 5;
    int lane = t & 31;
    int node = blockIdx.x * 8 + wi;
    if (node >= NN) return;

    const __half* h2 = (const __half*)d_h2pre;
    float dv = d_deg[node];
    float acc = __half2float(h2[node * 32 + lane]) * dv * dv;

    int beg = d_ptr[node], end = d_ptr[node + 1];
    for (int base = beg; base < end; base += 32) {
        if (base + lane < end) es[wi][lane] = d_csr[base + lane];
        __syncwarp();
        int cnt = end - base; if (cnt > 32) cnt = 32;
        for (int j = 0; j < cnt; j++) {
            int2 q = es[wi][j];
            acc = fmaf(__int_as_float(q.y), __half2float(h2[q.x * 32 + lane]), acc);
        }
        __syncwarp();
    }
    d_h2out[node * 32 + lane] = acc;
}

// ---------------- pooling: segment_max(relu(h2out + b2)), batch sorted ------
#define PN 16
__global__ void k_pool(const int* __restrict__ batch, const float* __restrict__ b2) {
    int tid = blockIdx.x * 256 + threadIdx.x;
    int c = tid & 31;
    int n0 = (tid >> 5) * PN;
    if (n0 >= NN) return;
    int nend = n0 + PN < NN ? n0 + PN : NN;
    float bb = b2[c];
    int g = batch[n0];
    float m = 0.0f;
    for (int n = n0; n < nend; n++) {
        int gn = batch[n];
        if (gn != g) {
            atomicMax((int*)&d_pooled[g * 32 + c], __float_as_int(m));
            g = gn; m = 0.0f;
        }
        float v = fmaxf(d_h2out[n * 32 + c] + bb, 0.0f);
        m = fmaxf(m, v);
    }
    atomicMax((int*)&d_pooled[g * 32 + c], __float_as_int(m));
}

// ---------------- final linear: out[64,4] = pooled @ Wlin + blin ------------
__global__ void k_final(const float* __restrict__ Wlin, const float* __restrict__ blin,
                        float* __restrict__ out) {
    int t = threadIdx.x;            // 256 = 64*4
    int g = t >> 2;
    int c = t & 3;
    float s = blin[c];
#pragma unroll
    for (int k = 0; k < 32; k++) s += d_pooled[g * 32 + k] * Wlin[k * 4 + c];
    out[g * 4 + c] = s;
}

// ---------------- launch -----------------------------------------------------
extern "C" void kernel_launch(void* const* d_in, const int* in_sizes, int n_in,
                              void* d_out, int out_size) {
    const float* x     = (const float*)d_in[0];
    const int*   ei    = (const int*)d_in[1];
    const float* ew    = (const float*)d_in[2];
    const int*   batch = (const int*)d_in[3];
    const float* W1    = (const float*)d_in[4];
    const float* b1    = (const float*)d_in[5];
    const float* W2    = (const float*)d_in[6];
    const float* b2    = (const float*)d_in[7];
    const float* Wlin  = (const float*)d_in[8];
    const float* blin  = (const float*)d_in[9];
    float* out = (float*)d_out;

    // fork: gemm1 (FMA-bound) on g_s2, CSR build (atomic/LSU-bound) on main.
    cudaEventRecord(g_evF, 0);
    cudaStreamWaitEvent(g_s2, g_evF, 0);
    k_gemm<256, 64, 1><<<(NN + 127) / 128, 256, 0, g_s2>>>(x, W1, nullptr);
    cudaEventRecord(g_evJ, g_s2);

    k_init<<<(NN + 255) / 256, 256>>>();
    k_hist<<<(NE + 255) / 256, 256>>>(ei, ew);
    k_scanA<<<NB, 256>>>();                                    // + rsqrt
    k_scanB<<<1, 128>>>();
    k_scanC<<<NB, 256>>>();
    k_scatter<<<(NE + 255) / 256, 256>>>(ei, ew);

    cudaStreamWaitEvent(0, g_evJ, 0);                          // join
    k_agg1<<<(NN + 7) / 8, 256>>>();

    k_gemm<64, 32, 2><<<(NN + 255) / 256, 256>>>(nullptr, W2, b1);
    k_agg2<<<(NN + 7) / 8, 256>>>();

    k_pool<<<((NN / PN + 1) * 32 + 255) / 256, 256>>>(batch, b2);
    k_final<<<1, 256>>>(Wlin, blin, out);
}

// round 13
// speedup vs baseline: 1.2123x; 1.0466x over previous
#include <cuda_runtime.h>
#include <cuda_fp16.h>

#define NN 100000
#define NE 3200000
#define NG 64
#define NB 100               // scan blocks
#define NPB 1000             // nodes per scan block (NB*NPB == NN)

typedef unsigned long long ull;

// ---------------- scratch (device globals; no allocations allowed) ----------
__device__ ull    d_degp[NN];         // packed: count<<40 | fixed(sum ew, Q2^30)
__device__ float  d_deg[NN];          // dinv = rsqrt(1 + sum ew)
__device__ int    d_cnt[NN];          // edge count per dst (written by scanA)
__device__ int    d_ptr[NN + 1];      // CSR row offsets
__device__ int    d_fill[NN];         // scatter cursors
__device__ int    d_bsum[NB];         // per-block count totals
__device__ int    d_boff[NB];         // exclusive block offsets
__device__ int2   d_csr[NE];          // {src, __float_as_int(ew * dinv[src])}
__device__ __half d_h1pre[NN * 64];   // x @ W1            (fp16 gather table)
__device__ float  d_h1out[NN * 64];   // conv1 aggregated  (fp32, read once)
__device__ __half d_h2pre[NN * 32];   // relu(h1out+b1)@W2 (fp16 gather table)
__device__ float  d_h2out[NN * 32];   // conv2 aggregated
__device__ float  d_pooled[NG * 32];

// --------- side stream + events for captured fork/join (created pre-main) ---
static cudaStream_t g_s2;
static cudaEvent_t  g_evF, g_evJ;
static struct StreamInit {
    StreamInit() {
        cudaStreamCreateWithFlags(&g_s2, cudaStreamNonBlocking);
        cudaEventCreateWithFlags(&g_evF, cudaEventDisableTiming);
        cudaEventCreateWithFlags(&g_evJ, cudaEventDisableTiming);
    }
} g_streamInit;

// ---------------- f32x2 helpers (Blackwell packed fp32) ---------------------
__device__ __forceinline__ ull pk2(float x) {
    ull r;
    asm("mov.b64 %0, {%1, %1};" : "=l"(r) : "f"(x));
    return r;
}
__device__ __forceinline__ void fma2(ull& d, ull a, ull b) {
    asm("fma.rn.f32x2 %0, %1, %2, %0;" : "+l"(d) : "l"(a), "l"(b));
}
__device__ __forceinline__ float2 up2(ull v) {
    float2 f;
    asm("mov.b64 {%0, %1}, %2;" : "=f"(f.x), "=f"(f.y) : "l"(v));
    return f;
}

// ---------------- init -------------------------------------------------------
__global__ void k_init() {
    int i = blockIdx.x * 256 + threadIdx.x;
    if (i < NN) d_degp[i] = 0ULL;
    if (i < NG * 32) d_pooled[i] = 0.0f;             // relu outputs >= 0
}

// ---------------- edge histogram: ONE packed 64-bit RED per edge -------------
__global__ void __launch_bounds__(256) k_hist(const int* __restrict__ ei,
                                              const float* __restrict__ ew) {
    int e = blockIdx.x * 256 + threadIdx.x;
    if (e >= NE) return;
    int d = ei[NE + e];
    ull pack = (1ULL << 40) | (ull)(ew[e] * 1073741824.0f);   // 2^30 fixed
    atomicAdd(&d_degp[d], pack);
}

// ---- scanA: unpack degp -> d_cnt + dinv, per-block count totals --------------
__global__ void __launch_bounds__(256) k_scanA() {
    __shared__ int sm[8];
    int b = blockIdx.x, t = threadIdx.x;
    int s = 0;
    for (int i = b * NPB + t; i < (b + 1) * NPB; i += 256) {
        ull v = d_degp[i];
        int cnt = (int)(v >> 40);
        float deg = 1.0f + (float)(v & ((1ULL << 40) - 1)) * (1.0f / 1073741824.0f);
        d_cnt[i] = cnt;
        d_deg[i] = rsqrtf(deg);
        s += cnt;
    }
#pragma unroll
    for (int o = 16; o; o >>= 1) s += __shfl_xor_sync(0xffffffffu, s, o);
    if ((t & 31) == 0) sm[t >> 5] = s;
    __syncthreads();
    if (t == 0) {
        int tot = 0;
#pragma unroll
        for (int i = 0; i < 8; i++) tot += sm[i];
        d_bsum[b] = tot;
    }
}

__global__ void __launch_bounds__(128) k_scanB() {    // scan 100 partials
    __shared__ int sm[128];
    int t = threadIdx.x;
    sm[t] = (t < NB) ? d_bsum[t] : 0;
    __syncthreads();
#pragma unroll
    for (int off = 1; off < 128; off <<= 1) {
        int v = (t >= off) ? sm[t - off] : 0;
        __syncthreads();
        sm[t] += v;
        __syncthreads();
    }
    if (t < NB) d_boff[t] = sm[t] - d_bsum[t];   // exclusive
    if (t == 0) d_ptr[NN] = NE;
}

__global__ void __launch_bounds__(256) k_scanC() {    // in-block scan + write
    __shared__ int sm[256];
    int b = blockIdx.x, t = threadIdx.x;
    int base = b * NPB;
    int4 c = make_int4(0, 0, 0, 0);
    if (t < NPB / 4) c = ((const int4*)(d_cnt + base))[t];
    int tsum = c.x + c.y + c.z + c.w;
    sm[t] = tsum;
    __syncthreads();
#pragma unroll
    for (int off = 1; off < 256; off <<= 1) {
        int v = (t >= off) ? sm[t - off] : 0;
        __syncthreads();
        sm[t] += v;
        __syncthreads();
    }
    if (t < NPB / 4) {
        int run = d_boff[b] + sm[t] - tsum;
        int i = base + t * 4;
        d_ptr[i] = run;     d_fill[i] = run;     run += c.x;
        d_ptr[i + 1] = run; d_fill[i + 1] = run; run += c.y;
        d_ptr[i + 2] = run; d_fill[i + 2] = run; run += c.z;
        d_ptr[i + 3] = run; d_fill[i + 3] = run;
    }
}

// ---- scatter: store {src, ew*dinv[src]} — dinv[dst] factored into agg -------
__global__ void k_scatter(const int* __restrict__ ei, const float* __restrict__ ew) {
    int e = blockIdx.x * 256 + threadIdx.x;
    if (e >= NE) return;
    int s = ei[e];
    int d = ei[NE + e];
    float w = ew[e] * d_deg[s];
    int pos = atomicAdd(&d_fill[d], 1);
    d_csr[pos] = make_int2(s, __float_as_int(w));
}

// ---------------- GEMM: C[n, COLS] = f(A[n, K]) @ W[K, COLS] ----------------
// MODE 1: A = x, C = d_h1pre (fp16). MODE 2: A = relu(d_h1out+b1), C = d_h2pre (fp16).
template <int K, int COLS, int MODE>
__global__ void __launch_bounds__(256) k_gemm(const float* __restrict__ Aarg,
                                              const float* __restrict__ W,
                                              const float* __restrict__ bias) {
    constexpr int CG = COLS / 4;
    constexpr int ROWS = (256 / CG) * 8;
    constexpr int KC = 64;
    __shared__ __align__(16) float Ws[KC * COLS];
    __shared__ __align__(16) float Bs[KC];
    const float* A = (MODE == 1) ? Aarg : d_h1out;

    int t = threadIdx.x;
    int ct = t % CG;
    int rt = t / CG;
    int row0 = blockIdx.x * ROWS + rt * 8;

    const float* ap[8];
#pragma unroll
    for (int i = 0; i < 8; i++) {
        int r = row0 + i;
        if (r > NN - 1) r = NN - 1;
        ap[i] = A + (long long)r * K;
    }

    ull acc[8][2];
#pragma unroll
    for (int i = 0; i < 8; i++) { acc[i][0] = 0ULL; acc[i][1] = 0ULL; }

    for (int k0 = 0; k0 < K; k0 += KC) {
        __syncthreads();
        for (int i = t; i < KC * COLS / 4; i += 256)
            ((float4*)Ws)[i] = ((const float4*)(W + k0 * COLS))[i];
        if (MODE == 2) {
            if (t < KC) Bs[t] = bias[k0 + t];
        }
        __syncthreads();

#pragma unroll 2
        for (int kq = 0; kq < KC / 4; kq++) {
            float4 a[8];
#pragma unroll
            for (int i = 0; i < 8; i++) a[i] = *(const float4*)(ap[i] + k0 + kq * 4);
            if (MODE == 2) {
                float4 b4 = *(const float4*)(Bs + kq * 4);
#pragma unroll
                for (int i = 0; i < 8; i++) {
                    a[i].x = fmaxf(a[i].x + b4.x, 0.0f);
                    a[i].y = fmaxf(a[i].y + b4.y, 0.0f);
                    a[i].z = fmaxf(a[i].z + b4.z, 0.0f);
                    a[i].w = fmaxf(a[i].w + b4.w, 0.0f);
                }
            }
#pragma unroll
            for (int j = 0; j < 4; j++) {
                ulonglong2 w2 = *(const ulonglong2*)(Ws + (kq * 4 + j) * COLS + ct * 4);
#pragma unroll
                for (int i = 0; i < 8; i++) {
                    float av = (j == 0) ? a[i].x : (j == 1) ? a[i].y
                             : (j == 2) ? a[i].z : a[i].w;
                    ull aa = pk2(av);
                    fma2(acc[i][0], aa, w2.x);
                    fma2(acc[i][1], aa, w2.y);
                }
            }
        }
    }

    __half2* C = (MODE == 1) ? (__half2*)d_h1pre : (__half2*)d_h2pre;
#pragma unroll
    for (int i = 0; i < 8; i++) {
        int r = row0 + i;
        if (r < NN) {
            float2 p0 = up2(acc[i][0]);
            float2 p1 = up2(acc[i][1]);
            C[r * (COLS / 2) + ct * 2]     = __floats2half2_rn(p0.x, p0.y);
            C[r * (COLS / 2) + ct * 2 + 1] = __floats2half2_rn(p1.x, p1.y);
        }
    }
}

// -------- agg1: CSR gather (fp16 table), warp/node, smem-staged --------------
// out = dinv_d * ( sum_e w'_e h[s_e]  +  dinv_d * h[node] )
__global__ void __launch_bounds__(256) k_agg1() {
    __shared__ int2 es[8][32];
    int t = threadIdx.x;
    int wi = t >> 5;
    int lane = t & 31;
    int node = blockIdx.x * 8 + wi;
    if (node >= NN) return;

    const __half2* h1 = (const __half2*)d_h1pre;   // 32 half2 per node row
    float dv = d_deg[node];
    float2 acc;
    {
        float2 v = __half22float2(h1[node * 32 + lane]);
        acc.x = v.x * dv;
        acc.y = v.y * dv;
    }

    int beg = d_ptr[node], end = d_ptr[node + 1];
    for (int base = beg; base < end; base += 32) {
        if (base + lane < end) es[wi][lane] = d_csr[base + lane];
        __syncwarp();
        int cnt = end - base; if (cnt > 32) cnt = 32;
        for (int j = 0; j < cnt; j++) {
            int2 q = es[wi][j];                       // broadcast LDS.64
            float w = __int_as_float(q.y);
            float2 v = __half22float2(h1[q.x * 32 + lane]);
            acc.x = fmaf(w, v.x, acc.x);
            acc.y = fmaf(w, v.y, acc.y);
        }
        __syncwarp();
    }
    acc.x *= dv;
    acc.y *= dv;
    ((float2*)d_h1out)[node * 32 + lane] = acc;
}

// -------- agg2: CSR gather (fp16 table), warp/node, smem-staged --------------
__global__ void __launch_bounds__(256) k_agg2() {
    __shared__ int2 es[8][32];
    int t = threadIdx.x;
    int wi = t >> 5;
    int lane = t & 31;
    int node = blockIdx.x * 8 + wi;
    if (node >= NN) return;

    const __half* h2 = (const __half*)d_h2pre;
    float dv = d_deg[node];
    float acc = __half2float(h2[node * 32 + lane]) * dv;

    int beg = d_ptr[node], end = d_ptr[node + 1];
    for (int base = beg; base < end; base += 32) {
        if (base + lane < end) es[wi][lane] = d_csr[base + lane];
        __syncwarp();
        int cnt = end - base; if (cnt > 32) cnt = 32;
        for (int j = 0; j < cnt; j++) {
            int2 q = es[wi][j];
            acc = fmaf(__int_as_float(q.y), __half2float(h2[q.x * 32 + lane]), acc);
        }
        __syncwarp();
    }
    d_h2out[node * 32 + lane] = acc * dv;
}

// ---------------- pooling: segment_max(relu(h2out + b2)), batch sorted ------
#define PN 16
__global__ void k_pool(const int* __restrict__ batch, const float* __restrict__ b2) {
    int tid = blockIdx.x * 256 + threadIdx.x;
    int c = tid & 31;
    int n0 = (tid >> 5) * PN;
    if (n0 >= NN) return;
    int nend = n0 + PN < NN ? n0 + PN : NN;
    float bb = b2[c];
    int g = batch[n0];
    float m = 0.0f;
    for (int n = n0; n < nend; n++) {
        int gn = batch[n];
        if (gn != g) {
            atomicMax((int*)&d_pooled[g * 32 + c], __float_as_int(m));
            g = gn; m = 0.0f;
        }
        float v = fmaxf(d_h2out[n * 32 + c] + bb, 0.0f);
        m = fmaxf(m, v);
    }
    atomicMax((int*)&d_pooled[g * 32 + c], __float_as_int(m));
}

// ---------------- final linear: out[64,4] = pooled @ Wlin + blin ------------
__global__ void k_final(const float* __restrict__ Wlin, const float* __restrict__ blin,
                        float* __restrict__ out) {
    int t = threadIdx.x;            // 256 = 64*4
    int g = t >> 2;
    int c = t & 3;
    float s = blin[c];
#pragma unroll
    for (int k = 0; k < 32; k++) s += d_pooled[g * 32 + k] * Wlin[k * 4 + c];
    out[g * 4 + c] = s;
}

// ---------------- launch -----------------------------------------------------
extern "C" void kernel_launch(void* const* d_in, const int* in_sizes, int n_in,
                              void* d_out, int out_size) {
    const float* x     = (const float*)d_in[0];
    const int*   ei    = (const int*)d_in[1];
    const float* ew    = (const float*)d_in[2];
    const int*   batch = (const int*)d_in[3];
    const float* W1    = (const float*)d_in[4];
    const float* b1    = (const float*)d_in[5];
    const float* W2    = (const float*)d_in[6];
    const float* b2    = (const float*)d_in[7];
    const float* Wlin  = (const float*)d_in[8];
    const float* blin  = (const float*)d_in[9];
    float* out = (float*)d_out;

    // fork: gemm1 (FMA-bound) on g_s2, CSR build (atomic/LSU-bound) on main.
    cudaEventRecord(g_evF, 0);
    cudaStreamWaitEvent(g_s2, g_evF, 0);
    k_gemm<256, 64, 1><<<(NN + 127) / 128, 256, 0, g_s2>>>(x, W1, nullptr);
    cudaEventRecord(g_evJ, g_s2);

    k_init<<<(NN + 255) / 256, 256>>>();
    k_hist<<<(NE + 255) / 256, 256>>>(ei, ew);
    k_scanA<<<NB, 256>>>();                                    // unpack + rsqrt
    k_scanB<<<1, 128>>>();
    k_scanC<<<NB, 256>>>();
    k_scatter<<<(NE + 255) / 256, 256>>>(ei, ew);

    cudaStreamWaitEvent(0, g_evJ, 0);                          // join
    k_agg1<<<(NN + 7) / 8, 256>>>();

    k_gemm<64, 32, 2><<<(NN + 255) / 256, 256>>>(nullptr, W2, b1);
    k_agg2<<<(NN + 7) / 8, 256>>>();

    k_pool<<<((NN / PN + 1) * 32 + 255) / 256, 256>>>(batch, b2);
    k_final<<<1, 256>>>(Wlin, blin, out);
}

// round 15
// speedup vs baseline: 1.4828x; 1.2232x over previous
#include <cuda_runtime.h>
#include <cuda_fp16.h>
#include <cstdint>

#define NN 100000
#define NE 3200000
#define NG 64
#define NB 100               // scan blocks
#define NPB 1000             // nodes per scan block (NB*NPB == NN)

typedef unsigned long long ull;

// ---------------- scratch (device globals; no allocations allowed) ----------
__device__ ull    d_degp[NN];         // packed: count<<40 | fixed(sum ew, Q2^30)
__device__ float  d_deg[NN];          // dinv = rsqrt(1 + sum ew)
__device__ int    d_cnt[NN];          // edge count per dst (written by scanA)
__device__ int    d_ptr[NN + 1];      // CSR row offsets
__device__ int    d_fill[NN];         // scatter cursors
__device__ int    d_bsum[NB];         // per-block count totals
__device__ int    d_boff[NB];         // exclusive block offsets
__device__ int2   d_csr[NE];          // {src, __float_as_int(ew * dinv[src])}
__device__ __half d_h1pre[NN * 64];   // x @ W1            (fp16 gather table)
__device__ float  d_h1out[NN * 64];   // conv1 aggregated  (fp32, read once)
__device__ __half d_h2pre[NN * 32];   // relu(h1out+b1)@W2 (fp16 gather table)
__device__ float  d_h2out[NN * 32];   // conv2 aggregated
__device__ float  d_pooled[NG * 32];

// --------- side stream + events for captured fork/join (created pre-main) ---
static cudaStream_t g_s2;
static cudaEvent_t  g_evF, g_evJ;
static struct StreamInit {
    StreamInit() {
        cudaStreamCreateWithFlags(&g_s2, cudaStreamNonBlocking);
        cudaEventCreateWithFlags(&g_evF, cudaEventDisableTiming);
        cudaEventCreateWithFlags(&g_evJ, cudaEventDisableTiming);
    }
} g_streamInit;

// ---------------- f32x2 helpers (Blackwell packed fp32) ---------------------
__device__ __forceinline__ ull pk2(float x) {
    ull r;
    asm("mov.b64 %0, {%1, %1};" : "=l"(r) : "f"(x));
    return r;
}
__device__ __forceinline__ void fma2(ull& d, ull a, ull b) {
    asm("fma.rn.f32x2 %0, %1, %2, %0;" : "+l"(d) : "l"(a), "l"(b));
}
__device__ __forceinline__ float2 up2(ull v) {
    float2 f;
    asm("mov.b64 {%0, %1}, %2;" : "=f"(f.x), "=f"(f.y) : "l"(v));
    return f;
}

// ---------------- mma.sync helpers (fp16 in, fp32 accum) ---------------------
__device__ __forceinline__ void ldm_x4(uint32_t& r0, uint32_t& r1,
                                       uint32_t& r2, uint32_t& r3, uint32_t a) {
    asm volatile("ldmatrix.sync.aligned.m8n8.x4.shared.b16 {%0,%1,%2,%3}, [%4];"
                 : "=r"(r0), "=r"(r1), "=r"(r2), "=r"(r3) : "r"(a));
}
__device__ __forceinline__ void ldm_x4t(uint32_t& r0, uint32_t& r1,
                                        uint32_t& r2, uint32_t& r3, uint32_t a) {
    asm volatile("ldmatrix.sync.aligned.m8n8.x4.trans.shared.b16 {%0,%1,%2,%3}, [%4];"
                 : "=r"(r0), "=r"(r1), "=r"(r2), "=r"(r3) : "r"(a));
}
__device__ __forceinline__ void mma16816(float* c, uint32_t a0, uint32_t a1,
                                         uint32_t a2, uint32_t a3,
                                         uint32_t b0, uint32_t b1) {
    asm volatile("mma.sync.aligned.m16n8k16.row.col.f32.f16.f16.f32 "
                 "{%0,%1,%2,%3}, {%4,%5,%6,%7}, {%8,%9}, {%0,%1,%2,%3};"
                 : "+f"(c[0]), "+f"(c[1]), "+f"(c[2]), "+f"(c[3])
                 : "r"(a0), "r"(a1), "r"(a2), "r"(a3), "r"(b0), "r"(b1));
}

// ---------------- init -------------------------------------------------------
__global__ void k_init() {
    int i = blockIdx.x * 256 + threadIdx.x;
    if (i < NN) d_degp[i] = 0ULL;
    if (i < NG * 32) d_pooled[i] = 0.0f;             // relu outputs >= 0
}

// ---------------- edge histogram: ONE packed 64-bit RED per edge -------------
__global__ void __launch_bounds__(256) k_hist(const int* __restrict__ ei,
                                              const float* __restrict__ ew) {
    int e = blockIdx.x * 256 + threadIdx.x;
    if (e >= NE) return;
    int d = ei[NE + e];
    ull pack = (1ULL << 40) | (ull)(ew[e] * 1073741824.0f);   // 2^30 fixed
    atomicAdd(&d_degp[d], pack);
}

// ---- scanA: unpack degp -> d_cnt + dinv, per-block count totals --------------
__global__ void __launch_bounds__(256) k_scanA() {
    __shared__ int sm[8];
    int b = blockIdx.x, t = threadIdx.x;
    int s = 0;
    for (int i = b * NPB + t; i < (b + 1) * NPB; i += 256) {
        ull v = d_degp[i];
        int cnt = (int)(v >> 40);
        float deg = 1.0f + (float)(v & ((1ULL << 40) - 1)) * (1.0f / 1073741824.0f);
        d_cnt[i] = cnt;
        d_deg[i] = rsqrtf(deg);
        s += cnt;
    }
#pragma unroll
    for (int o = 16; o; o >>= 1) s += __shfl_xor_sync(0xffffffffu, s, o);
    if ((t & 31) == 0) sm[t >> 5] = s;
    __syncthreads();
    if (t == 0) {
        int tot = 0;
#pragma unroll
        for (int i = 0; i < 8; i++) tot += sm[i];
        d_bsum[b] = tot;
    }
}

__global__ void __launch_bounds__(128) k_scanB() {    // scan 100 partials
    __shared__ int sm[128];
    int t = threadIdx.x;
    sm[t] = (t < NB) ? d_bsum[t] : 0;
    __syncthreads();
#pragma unroll
    for (int off = 1; off < 128; off <<= 1) {
        int v = (t >= off) ? sm[t - off] : 0;
        __syncthreads();
        sm[t] += v;
        __syncthreads();
    }
    if (t < NB) d_boff[t] = sm[t] - d_bsum[t];   // exclusive
    if (t == 0) d_ptr[NN] = NE;
}

__global__ void __launch_bounds__(256) k_scanC() {    // in-block scan + write
    __shared__ int sm[256];
    int b = blockIdx.x, t = threadIdx.x;
    int base = b * NPB;
    int4 c = make_int4(0, 0, 0, 0);
    if (t < NPB / 4) c = ((const int4*)(d_cnt + base))[t];
    int tsum = c.x + c.y + c.z + c.w;
    sm[t] = tsum;
    __syncthreads();
#pragma unroll
    for (int off = 1; off < 256; off <<= 1) {
        int v = (t >= off) ? sm[t - off] : 0;
        __syncthreads();
        sm[t] += v;
        __syncthreads();
    }
    if (t < NPB / 4) {
        int run = d_boff[b] + sm[t] - tsum;
        int i = base + t * 4;
        d_ptr[i] = run;     d_fill[i] = run;     run += c.x;
        d_ptr[i + 1] = run; d_fill[i + 1] = run; run += c.y;
        d_ptr[i + 2] = run; d_fill[i + 2] = run; run += c.z;
        d_ptr[i + 3] = run; d_fill[i + 3] = run;
    }
}

// ---- scatter: store {src, ew*dinv[src]} — dinv[dst] factored into agg -------
__global__ void k_scatter(const int* __restrict__ ei, const float* __restrict__ ew) {
    int e = blockIdx.x * 256 + threadIdx.x;
    if (e >= NE) return;
    int s = ei[e];
    int d = ei[NE + e];
    float w = ew[e] * d_deg[s];
    int pos = atomicAdd(&d_fill[d], 1);
    d_csr[pos] = make_int2(s, __float_as_int(w));
}

// ------- gemm1 via HMMA: d_h1pre[n,64] = fp16(x[n,256]) @ fp16(W1) -----------
// block: 128 rows x 64 cols, 8 warps (16 rows each), K chunks of 64 via smem.
__global__ void __launch_bounds__(256) k_gemm1_mma(const float* __restrict__ x,
                                                   const float* __restrict__ W1) {
    __shared__ __align__(16) __half xs[128][72];   // padded: conflict-free ldmatrix
    __shared__ __align__(16) __half ws[64][72];
    int t = threadIdx.x;
    int w = t >> 5, lane = t & 31;
    int row0 = blockIdx.x * 128;

    float acc[8][4];
#pragma unroll
    for (int i = 0; i < 8; i++)
#pragma unroll
        for (int j = 0; j < 4; j++) acc[i][j] = 0.0f;

    for (int k0 = 0; k0 < 256; k0 += 64) {
        __syncthreads();
        // x chunk: 128 rows x 64 cols (fp32 -> fp16)
        for (int i = t; i < 128 * 16; i += 256) {
            int r = i >> 4, c4 = i & 15;
            int rr = row0 + r; if (rr > NN - 1) rr = NN - 1;
            float4 v = *(const float4*)(x + (long long)rr * 256 + k0 + c4 * 4);
            __half2* dst = (__half2*)&xs[r][c4 * 4];
            dst[0] = __floats2half2_rn(v.x, v.y);
            dst[1] = __floats2half2_rn(v.z, v.w);
        }
        // W chunk: 64 rows x 64 cols
        for (int i = t; i < 64 * 16; i += 256) {
            int r = i >> 4, c4 = i & 15;
            float4 v = *(const float4*)(W1 + (k0 + r) * 64 + c4 * 4);
            __half2* dst = (__half2*)&ws[r][c4 * 4];
            dst[0] = __floats2half2_rn(v.x, v.y);
            dst[1] = __floats2half2_rn(v.z, v.w);
        }
        __syncthreads();

        uint32_t xs_b = (uint32_t)__cvta_generic_to_shared(&xs[0][0]);
        uint32_t ws_b = (uint32_t)__cvta_generic_to_shared(&ws[0][0]);
#pragma unroll
        for (int kk = 0; kk < 4; kk++) {
            uint32_t a0, a1, a2, a3;
            uint32_t aaddr = xs_b +
                (((w * 16 + (lane & 15)) * 72) + kk * 16 + ((lane >> 4) * 8)) * 2;
            ldm_x4(a0, a1, a2, a3, aaddr);
#pragma unroll
            for (int nb = 0; nb < 4; nb++) {
                uint32_t b0, b1, b2, b3;
                uint32_t baddr = ws_b +
                    (((kk * 16 + (lane & 15)) * 72) + nb * 16 + ((lane >> 4) * 8)) * 2;
                ldm_x4t(b0, b1, b2, b3, baddr);
                mma16816(acc[nb * 2],     a0, a1, a2, a3, b0, b1);
                mma16816(acc[nb * 2 + 1], a0, a1, a2, a3, b2, b3);
            }
        }
    }

    // epilogue: fragment -> d_h1pre (fp16)
    int g = lane >> 2, tg = lane & 3;
    __half2* C = (__half2*)d_h1pre;   // 32 half2 per row
    int r1 = row0 + w * 16 + g;
    int r2 = r1 + 8;
#pragma unroll
    for (int nt = 0; nt < 8; nt++) {
        int ci = nt * 4 + tg;
        if (r1 < NN) C[r1 * 32 + ci] = __floats2half2_rn(acc[nt][0], acc[nt][1]);
        if (r2 < NN) C[r2 * 32 + ci] = __floats2half2_rn(acc[nt][2], acc[nt][3]);
    }
}

// ---------------- gemm2: d_h2pre = relu(d_h1out + b1) @ W2 (FFMA2) -----------
__global__ void __launch_bounds__(256) k_gemm2(const float* __restrict__ W,
                                               const float* __restrict__ bias) {
    constexpr int K = 64, COLS = 32, CG = 8, KC = 64;   // ROWS = 256
    __shared__ __align__(16) float Ws[KC * COLS];
    __shared__ __align__(16) float Bs[KC];

    int t = threadIdx.x;
    int ct = t % CG;
    int rt = t / CG;
    int row0 = blockIdx.x * 256 + rt * 8;

    const float* ap[8];
#pragma unroll
    for (int i = 0; i < 8; i++) {
        int r = row0 + i;
        if (r > NN - 1) r = NN - 1;
        ap[i] = d_h1out + (long long)r * K;
    }

    ull acc[8][2];
#pragma unroll
    for (int i = 0; i < 8; i++) { acc[i][0] = 0ULL; acc[i][1] = 0ULL; }

    for (int i = t; i < KC * COLS / 4; i += 256)
        ((float4*)Ws)[i] = ((const float4*)W)[i];
    if (t < KC) Bs[t] = bias[t];
    __syncthreads();

#pragma unroll 2
    for (int kq = 0; kq < KC / 4; kq++) {
        float4 a[8];
#pragma unroll
        for (int i = 0; i < 8; i++) a[i] = *(const float4*)(ap[i] + kq * 4);
        float4 b4 = *(const float4*)(Bs + kq * 4);
#pragma unroll
        for (int i = 0; i < 8; i++) {
            a[i].x = fmaxf(a[i].x + b4.x, 0.0f);
            a[i].y = fmaxf(a[i].y + b4.y, 0.0f);
            a[i].z = fmaxf(a[i].z + b4.z, 0.0f);
            a[i].w = fmaxf(a[i].w + b4.w, 0.0f);
        }
#pragma unroll
        for (int j = 0; j < 4; j++) {
            ulonglong2 w2 = *(const ulonglong2*)(Ws + (kq * 4 + j) * COLS + ct * 4);
#pragma unroll
            for (int i = 0; i < 8; i++) {
                float av = (j == 0) ? a[i].x : (j == 1) ? a[i].y
                         : (j == 2) ? a[i].z : a[i].w;
                ull aa = pk2(av);
                fma2(acc[i][0], aa, w2.x);
                fma2(acc[i][1], aa, w2.y);
            }
        }
    }

    __half2* C = (__half2*)d_h2pre;
#pragma unroll
    for (int i = 0; i < 8; i++) {
        int r = row0 + i;
        if (r < NN) {
            float2 p0 = up2(acc[i][0]);
            float2 p1 = up2(acc[i][1]);
            C[r * (COLS / 2) + ct * 2]     = __floats2half2_rn(p0.x, p0.y);
            C[r * (COLS / 2) + ct * 2 + 1] = __floats2half2_rn(p1.x, p1.y);
        }
    }
}

// -------- agg1: CSR gather (fp16 table), warp/node, smem-staged --------------
// out = dinv_d * ( sum_e w'_e h[s_e]  +  dinv_d * h[node] )
__global__ void __launch_bounds__(256) k_agg1() {
    __shared__ int2 es[8][32];
    int t = threadIdx.x;
    int wi = t >> 5;
    int lane = t & 31;
    int node = blockIdx.x * 8 + wi;
    if (node >= NN) return;

    const __half2* h1 = (const __half2*)d_h1pre;   // 32 half2 per node row
    float dv = d_deg[node];
    float2 acc;
    {
        float2 v = __half22float2(h1[node * 32 + lane]);
        acc.x = v.x * dv;
        acc.y = v.y * dv;
    }

    int beg = d_ptr[node], end = d_ptr[node + 1];
    for (int base = beg; base < end; base += 32) {
        if (base + lane < end) es[wi][lane] = d_csr[base + lane];
        __syncwarp();
        int cnt = end - base; if (cnt > 32) cnt = 32;
        for (int j = 0; j < cnt; j++) {
            int2 q = es[wi][j];                       // broadcast LDS.64
            float w = __int_as_float(q.y);
            float2 v = __half22float2(h1[q.x * 32 + lane]);
            acc.x = fmaf(w, v.x, acc.x);
            acc.y = fmaf(w, v.y, acc.y);
        }
        __syncwarp();
    }
    acc.x *= dv;
    acc.y *= dv;
    ((float2*)d_h1out)[node * 32 + lane] = acc;
}

// -------- agg2: CSR gather (fp16 table), warp/node, smem-staged --------------
__global__ void __launch_bounds__(256) k_agg2() {
    __shared__ int2 es[8][32];
    int t = threadIdx.x;
    int wi = t >> 5;
    int lane = t & 31;
    int node = blockIdx.x * 8 + wi;
    if (node >= NN) return;

    const __half* h2 = (const __half*)d_h2pre;
    float dv = d_deg[node];
    float acc = __half2float(h2[node * 32 + lane]) * dv;

    int beg = d_ptr[node], end = d_ptr[node + 1];
    for (int base = beg; base < end; base += 32) {
        if (base + lane < end) es[wi][lane] = d_csr[base + lane];
        __syncwarp();
        int cnt = end - base; if (cnt > 32) cnt = 32;
        for (int j = 0; j < cnt; j++) {
            int2 q = es[wi][j];
            acc = fmaf(__int_as_float(q.y), __half2float(h2[q.x * 32 + lane]), acc);
        }
        __syncwarp();
    }
    d_h2out[node * 32 + lane] = acc * dv;
}

// ---------------- pooling: segment_max(relu(h2out + b2)), batch sorted ------
#define PN 16
__global__ void k_pool(const int* __restrict__ batch, const float* __restrict__ b2) {
    int tid = blockIdx.x * 256 + threadIdx.x;
    int c = tid & 31;
    int n0 = (tid >> 5) * PN;
    if (n0 >= NN) return;
    int nend = n0 + PN < NN ? n0 + PN : NN;
    float bb = b2[c];
    int g = batch[n0];
    float m = 0.0f;
    for (int n = n0; n < nend; n++) {
        int gn = batch[n];
        if (gn != g) {
            atomicMax((int*)&d_pooled[g * 32 + c], __float_as_int(m));
            g = gn; m = 0.0f;
        }
        float v = fmaxf(d_h2out[n * 32 + c] + bb, 0.0f);
        m = fmaxf(m, v);
    }
    atomicMax((int*)&d_pooled[g * 32 + c], __float_as_int(m));
}

// ---------------- final linear: out[64,4] = pooled @ Wlin + blin ------------
__global__ void k_final(const float* __restrict__ Wlin, const float* __restrict__ blin,
                        float* __restrict__ out) {
    int t = threadIdx.x;            // 256 = 64*4
    int g = t >> 2;
    int c = t & 3;
    float s = blin[c];
#pragma unroll
    for (int k = 0; k < 32; k++) s += d_pooled[g * 32 + k] * Wlin[k * 4 + c];
    out[g * 4 + c] = s;
}

// ---------------- launch -----------------------------------------------------
extern "C" void kernel_launch(void* const* d_in, const int* in_sizes, int n_in,
                              void* d_out, int out_size) {
    const float* x     = (const float*)d_in[0];
    const int*   ei    = (const int*)d_in[1];
    const float* ew    = (const float*)d_in[2];
    const int*   batch = (const int*)d_in[3];
    const float* W1    = (const float*)d_in[4];
    const float* b1    = (const float*)d_in[5];
    const float* W2    = (const float*)d_in[6];
    const float* b2    = (const float*)d_in[7];
    const float* Wlin  = (const float*)d_in[8];
    const float* blin  = (const float*)d_in[9];
    float* out = (float*)d_out;

    // fork: gemm1 (tensor) on g_s2, CSR build (atomic/LSU-bound) on main.
    cudaEventRecord(g_evF, 0);
    cudaStreamWaitEvent(g_s2, g_evF, 0);
    k_gemm1_mma<<<(NN + 127) / 128, 256, 0, g_s2>>>(x, W1);
    cudaEventRecord(g_evJ, g_s2);

    k_init<<<(NN + 255) / 256, 256>>>();
    k_hist<<<(NE + 255) / 256, 256>>>(ei, ew);
    k_scanA<<<NB, 256>>>();                                    // unpack + rsqrt
    k_scanB<<<1, 128>>>();
    k_scanC<<<NB, 256>>>();
    k_scatter<<<(NE + 255) / 256, 256>>>(ei, ew);

    cudaStreamWaitEvent(0, g_evJ, 0);                          // join
    k_agg1<<<(NN + 7) / 8, 256>>>();

    k_gemm2<<<(NN + 255) / 256, 256>>>(W2, b1);
    k_agg2<<<(NN + 7) / 8, 256>>>();

    k_pool<<<((NN / PN + 1) * 32 + 255) / 256, 256>>>(batch, b2);
    k_final<<<1, 256>>>(Wlin, blin, out);
}

// round 16
// speedup vs baseline: 1.4981x; 1.0103x over previous
#include <cuda_runtime.h>
#include <cuda_fp16.h>
#include <cstdint>

#define NN 100000
#define NE 3200000
#define NG 64
#define NB 100               // scan blocks
#define NPB 1000             // nodes per scan block (NB*NPB == NN)

typedef unsigned long long ull;

// ---------------- scratch (device globals; no allocations allowed) ----------
__device__ ull    d_degp[NN];         // packed: count<<40 | fixed(sum ew, Q2^30)
__device__ float  d_deg[NN];          // dinv = rsqrt(1 + sum ew)
__device__ int    d_cnt[NN];          // edge count per dst (written by scanA)
__device__ int    d_ptr[NN + 1];      // CSR row offsets
__device__ int    d_slot[NE];         // edge's arrival index within its dst
__device__ int    d_bsum[NB];         // per-block count totals
__device__ int    d_boff[NB];         // exclusive block offsets
__device__ int2   d_csr[NE];          // {src, __float_as_int(ew * dinv[src])}
__device__ __half d_h1pre[NN * 64];   // x @ W1            (fp16 gather table)
__device__ __half d_h1out[NN * 64];   // conv1 aggregated  (fp16, read once)
__device__ __half d_h2pre[NN * 32];   // relu(h1out+b1)@W2 (fp16 gather table)
__device__ float  d_h2out[NN * 32];   // conv2 aggregated
__device__ float  d_pooled[NG * 32];

// --------- side stream + events for captured fork/join (created pre-main) ---
static cudaStream_t g_s2;
static cudaEvent_t  g_evF, g_evJ;
static struct StreamInit {
    StreamInit() {
        cudaStreamCreateWithFlags(&g_s2, cudaStreamNonBlocking);
        cudaEventCreateWithFlags(&g_evF, cudaEventDisableTiming);
        cudaEventCreateWithFlags(&g_evJ, cudaEventDisableTiming);
    }
} g_streamInit;

// ---------------- f32x2 helpers (Blackwell packed fp32) ---------------------
__device__ __forceinline__ ull pk2(float x) {
    ull r;
    asm("mov.b64 %0, {%1, %1};" : "=l"(r) : "f"(x));
    return r;
}
__device__ __forceinline__ void fma2(ull& d, ull a, ull b) {
    asm("fma.rn.f32x2 %0, %1, %2, %0;" : "+l"(d) : "l"(a), "l"(b));
}
__device__ __forceinline__ float2 up2(ull v) {
    float2 f;
    asm("mov.b64 {%0, %1}, %2;" : "=f"(f.x), "=f"(f.y) : "l"(v));
    return f;
}

// ---------------- mma.sync helpers (fp16 in, fp32 accum) ---------------------
__device__ __forceinline__ void ldm_x4(uint32_t& r0, uint32_t& r1,
                                       uint32_t& r2, uint32_t& r3, uint32_t a) {
    asm volatile("ldmatrix.sync.aligned.m8n8.x4.shared.b16 {%0,%1,%2,%3}, [%4];"
                 : "=r"(r0), "=r"(r1), "=r"(r2), "=r"(r3) : "r"(a));
}
__device__ __forceinline__ void ldm_x4t(uint32_t& r0, uint32_t& r1,
                                        uint32_t& r2, uint32_t& r3, uint32_t a) {
    asm volatile("ldmatrix.sync.aligned.m8n8.x4.trans.shared.b16 {%0,%1,%2,%3}, [%4];"
                 : "=r"(r0), "=r"(r1), "=r"(r2), "=r"(r3) : "r"(a));
}
__device__ __forceinline__ void mma16816(float* c, uint32_t a0, uint32_t a1,
                                         uint32_t a2, uint32_t a3,
                                         uint32_t b0, uint32_t b1) {
    asm volatile("mma.sync.aligned.m16n8k16.row.col.f32.f16.f16.f32 "
                 "{%0,%1,%2,%3}, {%4,%5,%6,%7}, {%8,%9}, {%0,%1,%2,%3};"
                 : "+f"(c[0]), "+f"(c[1]), "+f"(c[2]), "+f"(c[3])
                 : "r"(a0), "r"(a1), "r"(a2), "r"(a3), "r"(b0), "r"(b1));
}

// ---------------- init -------------------------------------------------------
__global__ void k_init() {
    int i = blockIdx.x * 256 + threadIdx.x;
    if (i < NN) d_degp[i] = 0ULL;
    if (i < NG * 32) d_pooled[i] = 0.0f;             // relu outputs >= 0
}

// ------ edge histogram: packed 64-bit ATOM per edge; slot = old count -------
__global__ void __launch_bounds__(256) k_hist(const int* __restrict__ ei,
                                              const float* __restrict__ ew) {
    int e = blockIdx.x * 256 + threadIdx.x;
    if (e >= NE) return;
    int d = ei[NE + e];
    ull pack = (1ULL << 40) | (ull)(ew[e] * 1073741824.0f);   // 2^30 fixed
    ull old = atomicAdd(&d_degp[d], pack);
    d_slot[e] = (int)(old >> 40);
}

// ---- scanA: unpack degp -> d_cnt + dinv, per-block count totals --------------
__global__ void __launch_bounds__(256) k_scanA() {
    __shared__ int sm[8];
    int b = blockIdx.x, t = threadIdx.x;
    int s = 0;
    for (int i = b * NPB + t; i < (b + 1) * NPB; i += 256) {
        ull v = d_degp[i];
        int cnt = (int)(v >> 40);
        float deg = 1.0f + (float)(v & ((1ULL << 40) - 1)) * (1.0f / 1073741824.0f);
        d_cnt[i] = cnt;
        d_deg[i] = rsqrtf(deg);
        s += cnt;
    }
#pragma unroll
    for (int o = 16; o; o >>= 1) s += __shfl_xor_sync(0xffffffffu, s, o);
    if ((t & 31) == 0) sm[t >> 5] = s;
    __syncthreads();
    if (t == 0) {
        int tot = 0;
#pragma unroll
        for (int i = 0; i < 8; i++) tot += sm[i];
        d_bsum[b] = tot;
    }
}

__global__ void __launch_bounds__(128) k_scanB() {    // scan 100 partials
    __shared__ int sm[128];
    int t = threadIdx.x;
    sm[t] = (t < NB) ? d_bsum[t] : 0;
    __syncthreads();
#pragma unroll
    for (int off = 1; off < 128; off <<= 1) {
        int v = (t >= off) ? sm[t - off] : 0;
        __syncthreads();
        sm[t] += v;
        __syncthreads();
    }
    if (t < NB) d_boff[t] = sm[t] - d_bsum[t];   // exclusive
    if (t == 0) d_ptr[NN] = NE;
}

__global__ void __launch_bounds__(256) k_scanC() {    // in-block scan + write
    __shared__ int sm[256];
    int b = blockIdx.x, t = threadIdx.x;
    int base = b * NPB;
    int4 c = make_int4(0, 0, 0, 0);
    if (t < NPB / 4) c = ((const int4*)(d_cnt + base))[t];
    int tsum = c.x + c.y + c.z + c.w;
    sm[t] = tsum;
    __syncthreads();
#pragma unroll
    for (int off = 1; off < 256; off <<= 1) {
        int v = (t >= off) ? sm[t - off] : 0;
        __syncthreads();
        sm[t] += v;
        __syncthreads();
    }
    if (t < NPB / 4) {
        int run = d_boff[b] + sm[t] - tsum;
        int i = base + t * 4;
        d_ptr[i] = run;     run += c.x;
        d_ptr[i + 1] = run; run += c.y;
        d_ptr[i + 2] = run; run += c.z;
        d_ptr[i + 3] = run;
    }
}

// ---- scatter: pos = ptr[dst] + slot[e]; NO atomics --------------------------
__global__ void k_scatter(const int* __restrict__ ei, const float* __restrict__ ew) {
    int e = blockIdx.x * 256 + threadIdx.x;
    if (e >= NE) return;
    int s = ei[e];
    int d = ei[NE + e];
    float w = ew[e] * d_deg[s];
    int pos = d_ptr[d] + d_slot[e];
    d_csr[pos] = make_int2(s, __float_as_int(w));
}

// ------- gemm1 via HMMA: d_h1pre[n,64] = fp16(x[n,256]) @ fp16(W1) -----------
// block: 128 rows x 64 cols, 8 warps (16 rows each), K chunks of 64 via smem.
__global__ void __launch_bounds__(256) k_gemm1_mma(const float* __restrict__ x,
                                                   const float* __restrict__ W1) {
    __shared__ __align__(16) __half xs[128][72];   // padded: conflict-free ldmatrix
    __shared__ __align__(16) __half ws[64][72];
    int t = threadIdx.x;
    int w = t >> 5, lane = t & 31;
    int row0 = blockIdx.x * 128;

    float acc[8][4];
#pragma unroll
    for (int i = 0; i < 8; i++)
#pragma unroll
        for (int j = 0; j < 4; j++) acc[i][j] = 0.0f;

    for (int k0 = 0; k0 < 256; k0 += 64) {
        __syncthreads();
        // x chunk: 128 rows x 64 cols (fp32 -> fp16)
        for (int i = t; i < 128 * 16; i += 256) {
            int r = i >> 4, c4 = i & 15;
            int rr = row0 + r; if (rr > NN - 1) rr = NN - 1;
            float4 v = *(const float4*)(x + (long long)rr * 256 + k0 + c4 * 4);
            __half2* dst = (__half2*)&xs[r][c4 * 4];
            dst[0] = __floats2half2_rn(v.x, v.y);
            dst[1] = __floats2half2_rn(v.z, v.w);
        }
        // W chunk: 64 rows x 64 cols
        for (int i = t; i < 64 * 16; i += 256) {
            int r = i >> 4, c4 = i & 15;
            float4 v = *(const float4*)(W1 + (k0 + r) * 64 + c4 * 4);
            __half2* dst = (__half2*)&ws[r][c4 * 4];
            dst[0] = __floats2half2_rn(v.x, v.y);
            dst[1] = __floats2half2_rn(v.z, v.w);
        }
        __syncthreads();

        uint32_t xs_b = (uint32_t)__cvta_generic_to_shared(&xs[0][0]);
        uint32_t ws_b = (uint32_t)__cvta_generic_to_shared(&ws[0][0]);
#pragma unroll
        for (int kk = 0; kk < 4; kk++) {
            uint32_t a0, a1, a2, a3;
            uint32_t aaddr = xs_b +
                (((w * 16 + (lane & 15)) * 72) + kk * 16 + ((lane >> 4) * 8)) * 2;
            ldm_x4(a0, a1, a2, a3, aaddr);
#pragma unroll
            for (int nb = 0; nb < 4; nb++) {
                uint32_t b0, b1, b2, b3;
                uint32_t baddr = ws_b +
                    (((kk * 16 + (lane & 15)) * 72) + nb * 16 + ((lane >> 4) * 8)) * 2;
                ldm_x4t(b0, b1, b2, b3, baddr);
                mma16816(acc[nb * 2],     a0, a1, a2, a3, b0, b1);
                mma16816(acc[nb * 2 + 1], a0, a1, a2, a3, b2, b3);
            }
        }
    }

    // epilogue: fragment -> d_h1pre (fp16)
    int g = lane >> 2, tg = lane & 3;
    __half2* C = (__half2*)d_h1pre;   // 32 half2 per row
    int r1 = row0 + w * 16 + g;
    int r2 = r1 + 8;
#pragma unroll
    for (int nt = 0; nt < 8; nt++) {
        int ci = nt * 4 + tg;
        if (r1 < NN) C[r1 * 32 + ci] = __floats2half2_rn(acc[nt][0], acc[nt][1]);
        if (r2 < NN) C[r2 * 32 + ci] = __floats2half2_rn(acc[nt][2], acc[nt][3]);
    }
}

// ------- gemm2: d_h2pre = relu(fp16 d_h1out + b1) @ W2 (FFMA2) ---------------
__global__ void __launch_bounds__(256) k_gemm2(const float* __restrict__ W,
                                               const float* __restrict__ bias) {
    constexpr int K = 64, COLS = 32, CG = 8, KC = 64;   // ROWS = 256
    __shared__ __align__(16) float Ws[KC * COLS];
    __shared__ __align__(16) float Bs[KC];

    int t = threadIdx.x;
    int ct = t % CG;
    int rt = t / CG;
    int row0 = blockIdx.x * 256 + rt * 8;

    const __half* ap[8];
#pragma unroll
    for (int i = 0; i < 8; i++) {
        int r = row0 + i;
        if (r > NN - 1) r = NN - 1;
        ap[i] = d_h1out + (long long)r * K;
    }

    ull acc[8][2];
#pragma unroll
    for (int i = 0; i < 8; i++) { acc[i][0] = 0ULL; acc[i][1] = 0ULL; }

    for (int i = t; i < KC * COLS / 4; i += 256)
        ((float4*)Ws)[i] = ((const float4*)W)[i];
    if (t < KC) Bs[t] = bias[t];
    __syncthreads();

#pragma unroll 2
    for (int kq = 0; kq < KC / 4; kq++) {
        float4 a[8];
#pragma unroll
        for (int i = 0; i < 8; i++) {
            __half2 h0 = *(const __half2*)(ap[i] + kq * 4);
            __half2 h1 = *(const __half2*)(ap[i] + kq * 4 + 2);
            float2 f0 = __half22float2(h0);
            float2 f1 = __half22float2(h1);
            a[i] = make_float4(f0.x, f0.y, f1.x, f1.y);
        }
        float4 b4 = *(const float4*)(Bs + kq * 4);
#pragma unroll
        for (int i = 0; i < 8; i++) {
            a[i].x = fmaxf(a[i].x + b4.x, 0.0f);
            a[i].y = fmaxf(a[i].y + b4.y, 0.0f);
            a[i].z = fmaxf(a[i].z + b4.z, 0.0f);
            a[i].w = fmaxf(a[i].w + b4.w, 0.0f);
        }
#pragma unroll
        for (int j = 0; j < 4; j++) {
            ulonglong2 w2 = *(const ulonglong2*)(Ws + (kq * 4 + j) * COLS + ct * 4);
#pragma unroll
            for (int i = 0; i < 8; i++) {
                float av = (j == 0) ? a[i].x : (j == 1) ? a[i].y
                         : (j == 2) ? a[i].z : a[i].w;
                ull aa = pk2(av);
                fma2(acc[i][0], aa, w2.x);
                fma2(acc[i][1], aa, w2.y);
            }
        }
    }

    __half2* C = (__half2*)d_h2pre;
#pragma unroll
    for (int i = 0; i < 8; i++) {
        int r = row0 + i;
        if (r < NN) {
            float2 p0 = up2(acc[i][0]);
            float2 p1 = up2(acc[i][1]);
            C[r * (COLS / 2) + ct * 2]     = __floats2half2_rn(p0.x, p0.y);
            C[r * (COLS / 2) + ct * 2 + 1] = __floats2half2_rn(p1.x, p1.y);
        }
    }
}

// -------- agg1: CSR gather (fp16 table), warp/node, smem-staged --------------
// out = dinv_d * ( sum_e w'_e h[s_e]  +  dinv_d * h[node] ), stored fp16
__global__ void __launch_bounds__(256) k_agg1() {
    __shared__ int2 es[8][32];
    int t = threadIdx.x;
    int wi = t >> 5;
    int lane = t & 31;
    int node = blockIdx.x * 8 + wi;
    if (node >= NN) return;

    const __half2* h1 = (const __half2*)d_h1pre;   // 32 half2 per node row
    float dv = d_deg[node];
    float2 acc;
    {
        float2 v = __half22float2(h1[node * 32 + lane]);
        acc.x = v.x * dv;
        acc.y = v.y * dv;
    }

    int beg = d_ptr[node], end = d_ptr[node + 1];
    for (int base = beg; base < end; base += 32) {
        if (base + lane < end) es[wi][lane] = d_csr[base + lane];
        __syncwarp();
        int cnt = end - base; if (cnt > 32) cnt = 32;
        for (int j = 0; j < cnt; j++) {
            int2 q = es[wi][j];                       // broadcast LDS.64
            float w = __int_as_float(q.y);
            float2 v = __half22float2(h1[q.x * 32 + lane]);
            acc.x = fmaf(w, v.x, acc.x);
            acc.y = fmaf(w, v.y, acc.y);
        }
        __syncwarp();
    }
    ((__half2*)d_h1out)[node * 32 + lane] = __floats2half2_rn(acc.x * dv, acc.y * dv);
}

// -------- agg2: CSR gather (fp16 table), warp/node, smem-staged --------------
__global__ void __launch_bounds__(256) k_agg2() {
    __shared__ int2 es[8][32];
    int t = threadIdx.x;
    int wi = t >> 5;
    int lane = t & 31;
    int node = blockIdx.x * 8 + wi;
    if (node >= NN) return;

    const __half* h2 = (const __half*)d_h2pre;
    float dv = d_deg[node];
    float acc = __half2float(h2[node * 32 + lane]) * dv;

    int beg = d_ptr[node], end = d_ptr[node + 1];
    for (int base = beg; base < end; base += 32) {
        if (base + lane < end) es[wi][lane] = d_csr[base + lane];
        __syncwarp();
        int cnt = end - base; if (cnt > 32) cnt = 32;
        for (int j = 0; j < cnt; j++) {
            int2 q = es[wi][j];
            acc = fmaf(__int_as_float(q.y), __half2float(h2[q.x * 32 + lane]), acc);
        }
        __syncwarp();
    }
    d_h2out[node * 32 + lane] = acc * dv;
}

// ---------------- pooling: segment_max(relu(h2out + b2)), batch sorted ------
#define PN 16
__global__ void k_pool(const int* __restrict__ batch, const float* __restrict__ b2) {
    int tid = blockIdx.x * 256 + threadIdx.x;
    int c = tid & 31;
    int n0 = (tid >> 5) * PN;
    if (n0 >= NN) return;
    int nend = n0 + PN < NN ? n0 + PN : NN;
    float bb = b2[c];
    int g = batch[n0];
    float m = 0.0f;
    for (int n = n0; n < nend; n++) {
        int gn = batch[n];
        if (gn != g) {
            atomicMax((int*)&d_pooled[g * 32 + c], __float_as_int(m));
            g = gn; m = 0.0f;
        }
        float v = fmaxf(d_h2out[n * 32 + c] + bb, 0.0f);
        m = fmaxf(m, v);
    }
    atomicMax((int*)&d_pooled[g * 32 + c], __float_as_int(m));
}

// ---------------- final linear: out[64,4] = pooled @ Wlin + blin ------------
__global__ void k_final(const float* __restrict__ Wlin, const float* __restrict__ blin,
                        float* __restrict__ out) {
    int t = threadIdx.x;            // 256 = 64*4
    int g = t >> 2;
    int c = t & 3;
    float s = blin[c];
#pragma unroll
    for (int k = 0; k < 32; k++) s += d_pooled[g * 32 + k] * Wlin[k * 4 + c];
    out[g * 4 + c] = s;
}

// ---------------- launch -----------------------------------------------------
extern "C" void kernel_launch(void* const* d_in, const int* in_sizes, int n_in,
                              void* d_out, int out_size) {
    const float* x     = (const float*)d_in[0];
    const int*   ei    = (const int*)d_in[1];
    const float* ew    = (const float*)d_in[2];
    const int*   batch = (const int*)d_in[3];
    const float* W1    = (const float*)d_in[4];
    const float* b1    = (const float*)d_in[5];
    const float* W2    = (const float*)d_in[6];
    const float* b2    = (const float*)d_in[7];
    const float* Wlin  = (const float*)d_in[8];
    const float* blin  = (const float*)d_in[9];
    float* out = (float*)d_out;

    // fork: gemm1 (tensor) on g_s2, CSR build (atomic/LSU-bound) on main.
    cudaEventRecord(g_evF, 0);
    cudaStreamWaitEvent(g_s2, g_evF, 0);
    k_gemm1_mma<<<(NN + 127) / 128, 256, 0, g_s2>>>(x, W1);
    cudaEventRecord(g_evJ, g_s2);

    k_init<<<(NN + 255) / 256, 256>>>();
    k_hist<<<(NE + 255) / 256, 256>>>(ei, ew);
    k_scanA<<<NB, 256>>>();                                    // unpack + rsqrt
    k_scanB<<<1, 128>>>();
    k_scanC<<<NB, 256>>>();
    k_scatter<<<(NE + 255) / 256, 256>>>(ei, ew);

    cudaStreamWaitEvent(0, g_evJ, 0);                          // join
    k_agg1<<<(NN + 7) / 8, 256>>>();

    k_gemm2<<<(NN + 255) / 256, 256>>>(W2, b1);
    k_agg2<<<(NN + 7) / 8, 256>>>();

    k_pool<<<((NN / PN + 1) * 32 + 255) / 256, 256>>>(batch, b2);
    k_final<<<1, 256>>>(Wlin, blin, out);
}